// round 16
// baseline (speedup 1.0000x reference)
#include <cuda_runtime.h>
#include <cstdint>

// Problem constants
#define DDIM   512
#define EHEADS 64
#define VOUT   16
#define NBLOCKS 256
#define TILE_M 256                  // voxels per compute CTA (512 threads, b=8)
#define CAP    8192                 // per-head slot capacity
#define TPH    (CAP / TILE_M)       // 32 tiles per head
#define STEP_D 32                   // d per pipeline step (128B per row)
#define NSTEPS (DDIM / STEP_D)      // 16
#define XSTRIDE 36                  // floats per staged x row (144B, 16B-aligned)
#define XBUF   (TILE_M * XSTRIDE)   // 9216 floats per buffer
// smem floats: W 8192 + bias 16 + ridx 256 + 2 x-buffers 18432 = 26896
#define K4_SMEM_BYTES (26896 * 4)   // 107584 B -> 2 CTAs/SM = 32 warps/SM

// ---------------- scratch (device globals: no allocations allowed) ----------
__device__ int g_cursor[EHEADS];
__device__ int g_idx[EHEADS * CAP];

// ---------------- f32x2 helpers ----------------------------------------------
__device__ __forceinline__ void fma2(unsigned long long& d,
                                     unsigned long long a,
                                     unsigned long long b) {
    asm("fma.rn.f32x2 %0, %1, %2, %0;" : "+l"(d) : "l"(a), "l"(b));
}
__device__ __forceinline__ float unpack_sum(unsigned long long a) {
    float lo, hi;
    asm("mov.b64 {%0, %1}, %2;" : "=f"(lo), "=f"(hi) : "l"(a));
    return lo + hi;
}

// ---------------- cp.async helpers -------------------------------------------
__device__ __forceinline__ void cpa16(uint32_t dst_smem, const void* src) {
    asm volatile("cp.async.ca.shared.global [%0], [%1], 16;"
                 :: "r"(dst_smem), "l"(src));
}
__device__ __forceinline__ void cpa_commit() {
    asm volatile("cp.async.commit_group;");
}
template <int N>
__device__ __forceinline__ void cpa_wait() {
    asm volatile("cp.async.wait_group %0;" :: "n"(N));
}
__device__ __forceinline__ uint32_t s2u(const void* p) {
    return (uint32_t)__cvta_generic_to_shared(p);
}

// ---------------- K0: zero cursors -------------------------------------------
__global__ void k0_zero() { g_cursor[threadIdx.x] = 0; }

// ---------------- KS: scatter into fixed-capacity head buckets ---------------
__global__ void kS_scatter(const int* __restrict__ btg,
                           const int* __restrict__ b2h) {
    __shared__ int bh_s[NBLOCKS];
    __shared__ int cnt[EHEADS];
    __shared__ int base_s[EHEADS];
    int tid = threadIdx.x;
    bh_s[tid] = b2h[tid];
    if (tid < EHEADS) cnt[tid] = 0;
    __syncthreads();
    int gid = blockIdx.x * 256 + tid;
    int4 q = ((const int4*)btg)[gid];
    int h0 = bh_s[q.x], h1 = bh_s[q.y], h2 = bh_s[q.z], h3 = bh_s[q.w];
    int r0 = atomicAdd(&cnt[h0], 1);
    int r1 = atomicAdd(&cnt[h1], 1);
    int r2 = atomicAdd(&cnt[h2], 1);
    int r3 = atomicAdd(&cnt[h3], 1);
    __syncthreads();
    if (tid < EHEADS) base_s[tid] = atomicAdd(&g_cursor[tid], cnt[tid]);
    __syncthreads();
    int n = gid * 4;
    g_idx[h0 * CAP + base_s[h0] + r0] = n;
    g_idx[h1 * CAP + base_s[h1] + r1] = n + 1;
    g_idx[h2 * CAP + base_s[h2] + r2] = n + 2;
    g_idx[h3 * CAP + base_s[h3] + r3] = n + 3;
}

// ---------------- spacer so ncu capture (launch #4) lands on k4 --------------
__global__ void k_nop() {}

// ---------------- K4: 512 threads, 2 lanes/voxel (b=8), warp-private pipe ----
// CTA = 512 threads = 256 voxels. Lane pair (2l, 2l+1) shares voxel row
// w*16 + l; lane half = lane&1 computes outputs half*8..half*8+7 (acc = 16
// regs, fits 64-reg budget at 2 CTAs -> 32 warps/SM, occ 50%). Each warp
// stages its OWN 16 rows per step via private cp.async groups (4 full-line
// cpa16 per thread: 4 rows x 8 cols per instr -> 4 lines/instr, minimal
// wavefronts). No CTA barriers in the mainloop. W-LDS: 2 distinct addresses
// per warp (one per half) -> 2-phase; x-LDS: 16 pair-dedup'd rows -> 2-phase.
__global__ __launch_bounds__(512, 2)
void k4_compute(const float* __restrict__ x,
                const float* __restrict__ Wh,
                const float* __restrict__ bh,
                float* __restrict__ out) {
    extern __shared__ float smem[];
    float* Ws  = smem;                       // 8192 floats, natural [v][d]
    float* bs  = smem + 8192;                // 16 floats
    int*  ridx = (int*)(smem + 8208);        // 256 ints
    float* xb0 = smem + 8464;                // 9216 floats
    // xb1 = xb0 + XBUF

    int head  = blockIdx.x >> 5;             // TPH = 32
    int sbase = (blockIdx.x & (TPH - 1)) * TILE_M;
    int cnt = g_cursor[head];
    if (sbase >= cnt) return;
    int tid = threadIdx.x;
    int lane = tid & 31, w = tid >> 5;       // 16 warps

    // group 0: W[head] (2048 contiguous float4) + bias via cp.async
    {
        const float4* wsrc = (const float4*)(Wh + head * (VOUT * DDIM));
        uint32_t wdst = s2u(Ws) + tid * 16;
#pragma unroll
        for (int i = 0; i < 4; ++i)
            cpa16(wdst + i * 8192, (const void*)(wsrc + tid + i * 512));
        if (tid < 4)
            cpa16(s2u(bs) + tid * 16,
                  (const void*)((const float4*)(bh + head * VOUT) + tid));
    }
    cpa_commit();                            // group: W

    if (tid < TILE_M) {
        int slot = sbase + tid;
        ridx[tid] = (slot < cnt) ? g_idx[head * CAP + slot] : -1;
    }
    __syncthreads();                         // ridx visible

    // warp-private x staging: warp w owns rows w*16..w*16+15.
    // thread (rowb=lane>>3, c4=lane&7) stages rows rowb+4k (k=0..3), col c4.
    // Each cpa16 instr covers 4 full 128B lines (8 cols x 16B per row).
    int c4 = lane & 7;
    int rowb = lane >> 3;
    const float* srcrow[4];
#pragma unroll
    for (int k = 0; k < 4; ++k) {
        int v = ridx[w * 16 + rowb + 4 * k];
        if (v < 0) v = 0;                    // pad rows fetch row 0 (ignored)
        srcrow[k] = x + (size_t)v * DDIM + c4 * 4;
    }
    uint32_t xd0 = s2u(xb0) + ((w * 16 + rowb) * XSTRIDE + c4 * 4) * 4;
    uint32_t xd1 = xd0 + XBUF * 4;

    // stage step 0 (warp-private group)
#pragma unroll
    for (int k = 0; k < 4; ++k)
        cpa16(xd0 + k * (4 * XSTRIDE * 4), (const void*)srcrow[k]);
    cpa_commit();                            // group: x0

    cpa_wait<1>();                           // W complete (x0 may be pending)
    __syncthreads();                         // W visible CTA-wide

    int half = lane & 1;
    int myrow = w * 16 + (lane >> 1);
    int voxme = ridx[myrow];
    const float* myx0 = xb0 + myrow * XSTRIDE;
    const float* wbase = Ws + (half * 8) * DDIM;

    unsigned long long acc[8];
#pragma unroll
    for (int i = 0; i < 8; ++i) acc[i] = 0ull;

#pragma unroll 1
    for (int s = 0; s < NSTEPS; ++s) {
        if (s < NSTEPS - 1) {                // prefetch step s+1 (other buffer)
            uint32_t nxt = ((s + 1) & 1) ? xd1 : xd0;
            int boff = (s + 1) * STEP_D;
#pragma unroll
            for (int k = 0; k < 4; ++k)
                cpa16(nxt + k * (4 * XSTRIDE * 4),
                      (const void*)(srcrow[k] + boff));
            cpa_commit();
            cpa_wait<1>();                   // step s complete (this warp)
        } else {
            cpa_wait<0>();
        }
        __syncwarp();                        // step-s data from all lanes visible

        const float* xbase = (s & 1) ? (myx0 + XBUF) : myx0;
        const float* wb = wbase + s * STEP_D;
#pragma unroll
        for (int c = 0; c < 8; ++c) {        // 4-d chunks within the step
            ulonglong2 xa = *(const ulonglong2*)(xbase + c * 4);  // pair-shared
#pragma unroll
            for (int v = 0; v < 8; ++v) {
                ulonglong2 wf = *(const ulonglong2*)(wb + v * DDIM + c * 4);
                fma2(acc[v], xa.x, wf.x);
                fma2(acc[v], xa.y, wf.y);
            }
        }
        __syncwarp();                        // before this warp reuses the buffer
    }

    if (voxme >= 0) {
        const float* bsf = bs + half * 8;
        float4* orow = (float4*)(out + (size_t)voxme * VOUT + half * 8);
#pragma unroll
        for (int q = 0; q < 2; ++q) {
            float4 r;
            r.x = unpack_sum(acc[q * 4 + 0]) + bsf[q * 4 + 0];
            r.y = unpack_sum(acc[q * 4 + 1]) + bsf[q * 4 + 1];
            r.z = unpack_sum(acc[q * 4 + 2]) + bsf[q * 4 + 2];
            r.w = unpack_sum(acc[q * 4 + 3]) + bsf[q * 4 + 3];
            orow[q] = r;
        }
    }
}

// ---------------- launch ------------------------------------------------------
extern "C" void kernel_launch(void* const* d_in, const int* in_sizes, int n_in,
                              void* d_out, int out_size) {
    const int*   btg = (const int*)d_in[0];     // block_type_grid (65536)
    const float* x   = (const float*)d_in[1];   // x (65536*512)
    const float* Wh  = (const float*)d_in[2];   // W_heads (64*16*512)
    const float* bh  = (const float*)d_in[3];   // b_heads (64*16)
    const int*   b2h = (const int*)d_in[4];     // block2head (256)
    float* out = (float*)d_out;

    cudaFuncSetAttribute(k4_compute,
                         cudaFuncAttributeMaxDynamicSharedMemorySize,
                         K4_SMEM_BYTES);

    k0_zero<<<1, EHEADS>>>();
    kS_scatter<<<64, 256>>>(btg, b2h);
    k_nop<<<1, 32>>>();   // ncu captures launch #4 -> k4_compute
    k4_compute<<<EHEADS * TPH, 512, K4_SMEM_BYTES>>>(x, Wh, bh, out);
}

// round 17
// speedup vs baseline: 1.3931x; 1.3931x over previous
#include <cuda_runtime.h>
#include <cstdint>

// Problem constants
#define DDIM   512
#define EHEADS 64
#define VOUT   16
#define NBLOCKS 256
#define TILE_M 128                  // voxels per compute CTA (128 threads)
#define CAP    8192                 // per-head slot capacity
#define TPH    (CAP / TILE_M)       // 64 tiles per head
#define STEP_D 16                   // d per pipeline step (64B per row)
#define NSTEPS (DDIM / STEP_D)      // 32
#define XSTRIDE 20                  // floats per staged x row (80B, 16B-aligned)
#define XBUF   (TILE_M * XSTRIDE)   // 2560 floats per buffer
// smem floats: W 8192 + bias 16 + ridx 128 + 2 x-buffers 5120 = 13456
#define K4_SMEM_BYTES (13456 * 4)   // 53824 B -> 4 CTAs/SM = 16 warps/SM

// ---------------- scratch (device globals: no allocations allowed) ----------
__device__ int g_cursor[EHEADS];
__device__ int g_idx[EHEADS * CAP];

// ---------------- f32x2 helpers ----------------------------------------------
__device__ __forceinline__ void fma2(unsigned long long& d,
                                     unsigned long long a,
                                     unsigned long long b) {
    asm("fma.rn.f32x2 %0, %1, %2, %0;" : "+l"(d) : "l"(a), "l"(b));
}
__device__ __forceinline__ float unpack_sum(unsigned long long a) {
    float lo, hi;
    asm("mov.b64 {%0, %1}, %2;" : "=f"(lo), "=f"(hi) : "l"(a));
    return lo + hi;
}

// ---------------- cp.async helpers -------------------------------------------
__device__ __forceinline__ void cpa16(uint32_t dst_smem, const void* src) {
    asm volatile("cp.async.ca.shared.global [%0], [%1], 16;"
                 :: "r"(dst_smem), "l"(src));
}
__device__ __forceinline__ void cpa_commit() {
    asm volatile("cp.async.commit_group;");
}
template <int N>
__device__ __forceinline__ void cpa_wait() {
    asm volatile("cp.async.wait_group %0;" :: "n"(N));
}
__device__ __forceinline__ uint32_t s2u(const void* p) {
    return (uint32_t)__cvta_generic_to_shared(p);
}

// ---------------- K0: zero cursors -------------------------------------------
__global__ void k0_zero() { g_cursor[threadIdx.x] = 0; }

// ---------------- KS: scatter into fixed-capacity head buckets ---------------
__global__ void kS_scatter(const int* __restrict__ btg,
                           const int* __restrict__ b2h) {
    __shared__ int bh_s[NBLOCKS];
    __shared__ int cnt[EHEADS];
    __shared__ int base_s[EHEADS];
    int tid = threadIdx.x;
    bh_s[tid] = b2h[tid];
    if (tid < EHEADS) cnt[tid] = 0;
    __syncthreads();
    int gid = blockIdx.x * 256 + tid;
    int4 q = ((const int4*)btg)[gid];
    int h0 = bh_s[q.x], h1 = bh_s[q.y], h2 = bh_s[q.z], h3 = bh_s[q.w];
    int r0 = atomicAdd(&cnt[h0], 1);
    int r1 = atomicAdd(&cnt[h1], 1);
    int r2 = atomicAdd(&cnt[h2], 1);
    int r3 = atomicAdd(&cnt[h3], 1);
    __syncthreads();
    if (tid < EHEADS) base_s[tid] = atomicAdd(&g_cursor[tid], cnt[tid]);
    __syncthreads();
    int n = gid * 4;
    g_idx[h0 * CAP + base_s[h0] + r0] = n;
    g_idx[h1 * CAP + base_s[h1] + r1] = n + 1;
    g_idx[h2 * CAP + base_s[h2] + r2] = n + 2;
    g_idx[h3 * CAP + base_s[h3] + r3] = n + 3;
}

// ---------------- spacer so ncu capture (launch #4) lands on k4 --------------
__global__ void k_nop() {}

// ---------------- K4: 128-thr CTA, 4 CTAs/SM, 4vox x 4v, warp-private pipe ---
// CTA = 128 threads = 128 voxels of one head; thread tile 4 voxels x 4 outputs
// (minimizes crossbar per FLOP at 32 acc regs). W interleaved [cc][vv][vgrp]
// (float4) -> warp W-LDS addresses 16B-consecutive: single wavefront.
// x staged in 16-d double-buffered steps, XSTRIDE=20 (20*voxgrp mod 32 all
// distinct -> conflict-free x-LDS). Each warp stages its OWN 32 rows via
// private cp.async groups: no CTA barriers in the mainloop. 53.8 KB smem
// -> 4 independent CTA pipelines per SM.
__global__ __launch_bounds__(128, 4)
void k4_compute(const float* __restrict__ x,
                const float* __restrict__ Wh,
                const float* __restrict__ bh,
                float* __restrict__ out) {
    extern __shared__ float smem[];
    float* Ws  = smem;                       // 8192 floats: float4[cc*16+vv*4+vgrp]
    float* bs  = smem + 8192;                // 16 floats
    int*  ridx = (int*)(smem + 8208);        // 128 ints
    float* xb0 = smem + 8336;                // 2560 floats
    // xb1 = xb0 + XBUF

    int head  = blockIdx.x >> 6;             // TPH = 64
    int sbase = (blockIdx.x & (TPH - 1)) * TILE_M;
    int cnt = g_cursor[head];
    if (sbase >= cnt) return;
    int tid = threadIdx.x;
    int lane = tid & 31, w = tid >> 5;       // 4 warps

    // group 0: W[head] into interleaved layout + bias via cp.async.
    // thread t: output row v = t>>3 (0..15), chunks cc = (t&7)*16 + i.
    {
        const float* wsrc = Wh + head * (VOUT * DDIM);
        int v  = tid >> 3;
        int cb = (tid & 7) * 16;
        uint32_t wbase = s2u(Ws);
        int dsub = (v & 3) * 4 + (v >> 2);   // vv*4 + vgrp
#pragma unroll
        for (int i = 0; i < 16; ++i) {
            int cc = cb + i;
            cpa16(wbase + (cc * 16 + dsub) * 16,
                  (const void*)(wsrc + v * DDIM + cc * 4));
        }
        if (tid < 4)
            cpa16(s2u(bs) + tid * 16,
                  (const void*)((const float4*)(bh + head * VOUT) + tid));
    }
    cpa_commit();                            // group: W

    int slot = sbase + tid;
    ridx[tid] = (slot < cnt) ? g_idx[head * CAP + slot] : -1;
    __syncthreads();                         // ridx visible

    // warp-private x staging: warp w owns rows w*32..w*32+31.
    // thread (rowb=lane>>2, c4=lane&3) stages rows rowb+8k (k=0..3), col c4.
    // Per step = 16 d = 4 float4 per row; instr k covers 8 rows x 64B.
    int c4 = lane & 3;
    int rowb = lane >> 2;
    const float* srcrow[4];
#pragma unroll
    for (int k = 0; k < 4; ++k) {
        int v = ridx[w * 32 + rowb + 8 * k];
        if (v < 0) v = 0;                    // pad rows fetch row 0 (ignored)
        srcrow[k] = x + (size_t)v * DDIM + c4 * 4;
    }
    uint32_t xd0 = s2u(xb0) + ((w * 32 + rowb) * XSTRIDE + c4 * 4) * 4;
    uint32_t xd1 = xd0 + XBUF * 4;

    // stage step 0 (warp-private group)
#pragma unroll
    for (int k = 0; k < 4; ++k)
        cpa16(xd0 + k * (8 * XSTRIDE * 4), (const void*)srcrow[k]);
    cpa_commit();                            // group: x0

    cpa_wait<1>();                           // W complete (x0 may be pending)
    __syncthreads();                         // W visible CTA-wide

    int vgrp = lane >> 3, voxgrp = lane & 7;
    const float* myx0 = xb0 + (w * 32 + voxgrp) * XSTRIDE;
    const float4* Ws4 = (const float4*)Ws;

    unsigned long long acc[16];
#pragma unroll
    for (int i = 0; i < 16; ++i) acc[i] = 0ull;

#pragma unroll 1
    for (int s = 0; s < NSTEPS; ++s) {
        if (s < NSTEPS - 1) {                // prefetch step s+1 (other buffer)
            uint32_t nxt = ((s + 1) & 1) ? xd1 : xd0;
            int boff = (s + 1) * STEP_D;
#pragma unroll
            for (int k = 0; k < 4; ++k)
                cpa16(nxt + k * (8 * XSTRIDE * 4),
                      (const void*)(srcrow[k] + boff));
            cpa_commit();
            cpa_wait<1>();                   // step s complete (this warp)
        } else {
            cpa_wait<0>();
        }
        __syncwarp();                        // step-s data from all lanes visible

        const float* xbase = (s & 1) ? (myx0 + XBUF) : myx0;
#pragma unroll
        for (int c = 0; c < 4; ++c) {        // 4-d chunks within the step
            int cc = s * 4 + c;
            ulonglong2 xf[4];
#pragma unroll
            for (int m = 0; m < 4; ++m)      // 4 voxels, rows strided by 8
                xf[m] = *(const ulonglong2*)(xbase + m * (8 * XSTRIDE) + c * 4);
#pragma unroll
            for (int vv = 0; vv < 4; ++vv) {
                float4 wq = Ws4[cc * 16 + vv * 4 + vgrp];  // single wavefront
                ulonglong2 wf = *(const ulonglong2*)&wq;
#pragma unroll
                for (int m = 0; m < 4; ++m) {
                    fma2(acc[vv * 4 + m], xf[m].x, wf.x);
                    fma2(acc[vv * 4 + m], xf[m].y, wf.y);
                }
            }
        }
        __syncwarp();                        // before this warp reuses the buffer
    }

    float4 bv = *(const float4*)(bs + vgrp * 4);
#pragma unroll
    for (int m = 0; m < 4; ++m) {
        int vox = ridx[w * 32 + m * 8 + voxgrp];
        if (vox >= 0) {
            float4 o;
            o.x = unpack_sum(acc[0 * 4 + m]) + bv.x;
            o.y = unpack_sum(acc[1 * 4 + m]) + bv.y;
            o.z = unpack_sum(acc[2 * 4 + m]) + bv.z;
            o.w = unpack_sum(acc[3 * 4 + m]) + bv.w;
            ((float4*)out)[(size_t)vox * 4 + vgrp] = o;
        }
    }
}

// ---------------- launch ------------------------------------------------------
extern "C" void kernel_launch(void* const* d_in, const int* in_sizes, int n_in,
                              void* d_out, int out_size) {
    const int*   btg = (const int*)d_in[0];     // block_type_grid (65536)
    const float* x   = (const float*)d_in[1];   // x (65536*512)
    const float* Wh  = (const float*)d_in[2];   // W_heads (64*16*512)
    const float* bh  = (const float*)d_in[3];   // b_heads (64*16)
    const int*   b2h = (const int*)d_in[4];     // block2head (256)
    float* out = (float*)d_out;

    cudaFuncSetAttribute(k4_compute,
                         cudaFuncAttributeMaxDynamicSharedMemorySize,
                         K4_SMEM_BYTES);

    k0_zero<<<1, EHEADS>>>();
    kS_scatter<<<64, 256>>>(btg, b2h);
    k_nop<<<1, 32>>>();   // ncu captures launch #4 -> k4_compute
    k4_compute<<<EHEADS * TPH, 128, K4_SMEM_BYTES>>>(x, Wh, bh, out);
}